// round 17
// baseline (speedup 1.0000x reference)
#include <cuda_runtime.h>
#include <cuda_fp16.h>
#include <cstdint>

// GRU fused kernel v10b: B=16, T=60, S=2000, C=64, H=64.
// v9 numerics (fp16 weights/activations, MUFU.TANH activations, f32 h state)
// with warp-PAIR structure for B-operand reuse: warps (2p,2p+1) share 32
// sequence rows; each warp owns 32 of 64 gate-cols for all of r/z/n. Every
// ldsm4'd B fragment feeds 4 mmas (M=32) instead of 2 (M=16), halving the
// smem-crossbar traffic that was the #1 pipe (L1=65.6%) in v9.
// v10b FIX: x-pointer batch decomposition is done per 8-row group
// (2000 % 8 == 0) instead of per 32-row pair tile (2000 % 32 == 16), which
// made boundary-straddling pairs read the wrong batch in v10 (rel_err 9e-2).

namespace {

constexpr int kT = 60, kS = 2000, kC = 64, kH = 64, kG = 192;
constexpr int PITCH = 72;      // fp16 elems per smem row (144B) -> conflict-free ldsm
constexpr int THREADS = 256;   // 8 warps = 4 pairs x 32 rows = 128 rows per CTA
constexpr int NROWS = 16 * 2000;

constexpr int OFF_WIH = 0;
constexpr int OFF_WHH = OFF_WIH + kG * PITCH * 2;   // 27648
constexpr int OFF_BRZ = OFF_WHH + kG * PITCH * 2;   // 55296  f32[128] (pre-scaled 0.5)
constexpr int OFF_BIN = OFF_BRZ + 128 * 4;          // f32[64]
constexpr int OFF_BHN = OFF_BIN + 64 * 4;           // f32[64]
constexpr int OFF_HX = OFF_BHN + 64 * 4;            // 4 pair buffers, 32 rows each
constexpr int HX_PAIR = 32 * PITCH * 2;             // 4608 B
constexpr int SMEM_BYTES = OFF_HX + 4 * HX_PAIR;    // 74752 B

__device__ __forceinline__ uint32_t smem_u32(const void* p) {
  return (uint32_t)__cvta_generic_to_shared(p);
}

__device__ __forceinline__ void ldsm4(uint32_t r[4], uint32_t addr) {
  asm volatile("ldmatrix.sync.aligned.m8n8.x4.shared.b16 {%0,%1,%2,%3}, [%4];\n"
               : "=r"(r[0]), "=r"(r[1]), "=r"(r[2]), "=r"(r[3]) : "r"(addr));
}

__device__ __forceinline__ void mma16816(float d[4], const uint32_t a[4],
                                         const uint32_t b0, const uint32_t b1) {
  asm volatile(
      "mma.sync.aligned.m16n8k16.row.col.f32.f16.f16.f32 "
      "{%0,%1,%2,%3},{%4,%5,%6,%7},{%8,%9},{%0,%1,%2,%3};\n"
      : "+f"(d[0]), "+f"(d[1]), "+f"(d[2]), "+f"(d[3])
      : "r"(a[0]), "r"(a[1]), "r"(a[2]), "r"(a[3]), "r"(b0), "r"(b1));
}

__device__ __forceinline__ uint32_t pack_f16x2(float a, float b) {
  __half2 h = __floats2half2_rn(a, b);
  return *reinterpret_cast<uint32_t*>(&h);
}

__device__ __forceinline__ float ftanh(float x) {
  float r;
  asm("tanh.approx.f32 %0, %1;" : "=f"(r) : "f"(x));
  return r;
}
// sigmoid(2y) = 0.5*tanh(y) + 0.5 ; caller passes y = 0.5*g + (0.5*b)
__device__ __forceinline__ float fsigmoid_half(float y) {
  return fmaf(0.5f, ftanh(y), 0.5f);
}

}  // namespace

__global__ void __launch_bounds__(THREADS, 1)
gru_fused_kernel(const float* __restrict__ chars,
                 const float* __restrict__ Wih,
                 const float* __restrict__ Whh,
                 const float* __restrict__ bih,
                 const float* __restrict__ bhh,
                 float* __restrict__ out) {
  extern __shared__ char smem[];
  __half* wih_s = reinterpret_cast<__half*>(smem + OFF_WIH);
  __half* whh_s = reinterpret_cast<__half*>(smem + OFF_WHH);
  float* brz = reinterpret_cast<float*>(smem + OFF_BRZ);
  float* bin_s = reinterpret_cast<float*>(smem + OFF_BIN);
  float* bhn_s = reinterpret_cast<float*>(smem + OFF_BHN);

  const int tid = threadIdx.x;
  const int lane = tid & 31;
  const int wid = tid >> 5;
  const int pair = wid >> 1;   // 0..3
  const int q = wid & 1;       // column half owner: cols 32q..32q+31 per gate
  const int barid = pair + 1;  // named barrier per pair (64 threads)

  // ---- one-time init: fp16 weights (padded pitch), biases ----
  for (int i = tid; i < kG * kC; i += THREADS) {
    const int g = i >> 6, c = i & 63;
    wih_s[g * PITCH + c] = __float2half_rn(Wih[i]);
    whh_s[g * PITCH + c] = __float2half_rn(Whh[i]);
  }
  // r/z bias pre-scaled by 0.5 for the sigmoid-via-tanh identity
  if (tid < 128) brz[tid] = 0.5f * (bih[tid] + bhh[tid]);
  if (tid < 64) {
    bin_s[tid] = bih[128 + tid];
    bhn_s[tid] = bhh[128 + tid];
  }
  __syncthreads();  // the only block-wide barrier

  // ---- per-pair geometry: 32 rows shared by the two warps ----
  const int pr0 = blockIdx.x * 128 + pair * 32;
  const int lr = lane >> 2;          // 0..7
  const int c0 = (lane & 3) * 2;     // 0,2,4,6

  // x row pointers for 8-row groups r4 = 0..3 (base rows pr0, pr0+8, +16, +24).
  // Batch decomposition PER GROUP: 2000 % 8 == 0, so an 8-row group never
  // straddles a batch boundary (32-row tiles do: 2000 % 32 == 16).
  const float* px[4];
#pragma unroll
  for (int r4 = 0; r4 < 4; ++r4) {
    const int n0 = pr0 + 8 * r4;
    const int b4 = n0 / kS;
    const int s4 = n0 - b4 * kS;
    px[r4] = chars + ((size_t)b4 * kT * kS + (s4 + lr)) * (size_t)kC;
  }
  const size_t tstride = (size_t)kS * kC;

  // B-fragment ldsm lane offset; base includes this warp's 32-col slice (q)
  const int sel = lane >> 3;
  const int b_lane_off = ((lane & 7) + 8 * (sel >> 1)) * (PITCH * 2) + (sel & 1) * 16;
  const uint32_t wih_b = smem_u32(wih_s) + b_lane_off + q * 32 * (PITCH * 2);
  const uint32_t whh_b = smem_u32(whh_s) + b_lane_off + q * 32 * (PITCH * 2);

  // h exchange buffer for this pair (32 rows x 64 cols fp16, pitch 72)
  __half* hx = reinterpret_cast<__half*>(smem + OFF_HX + pair * HX_PAIR);
  const uint32_t hx_u32 = smem_u32(hx);
  // A-frag ldsm address into hx (per m-tile of 16 rows)
  const uint32_t hx_a_off = (lane & 15) * (PITCH * 2) + ((lane >> 4) << 4);

  // h state: this warp's 32 cols x 32 rows, f32 C-fragment layout.
  // hf[mt*4+jj][e]: m-tile mt (rows 16mt..16mt+15), col-tile jj (cols 32q+8jj..),
  // e: (lr,c0),(lr,c0+1),(lr+8,c0),(lr+8,c0+1)
  float hf[8][4];
#pragma unroll
  for (int j = 0; j < 8; ++j)
#pragma unroll
    for (int e = 0; e < 4; ++e) hf[j][e] = 0.0f;

  for (int t = 0; t < kT; ++t) {
    // ---- accumulators (zero-init; bias added in EW) ----
    float accR[8][4], accZ[8][4], accN[8][4], accHN[8][4];
#pragma unroll
    for (int j = 0; j < 8; ++j)
#pragma unroll
      for (int e = 0; e < 4; ++e) {
        accR[j][e] = 0.0f; accZ[j][e] = 0.0f;
        accN[j][e] = 0.0f; accHN[j][e] = 0.0f;
      }

    // ---- load x_t (32 rows) and pack to fp16 A-fragments ----
    {
      uint32_t xa[2][4][4];  // [mt][kk][frag]
#pragma unroll
      for (int kk = 0; kk < 4; ++kk)
#pragma unroll
        for (int mt = 0; mt < 2; ++mt) {
          const float2 v0 = *reinterpret_cast<const float2*>(px[2 * mt] + 16 * kk + c0);
          const float2 v1 = *reinterpret_cast<const float2*>(px[2 * mt + 1] + 16 * kk + c0);
          const float2 v2 = *reinterpret_cast<const float2*>(px[2 * mt] + 16 * kk + 8 + c0);
          const float2 v3 = *reinterpret_cast<const float2*>(px[2 * mt + 1] + 16 * kk + 8 + c0);
          xa[mt][kk][0] = pack_f16x2(v0.x, v0.y);
          xa[mt][kk][1] = pack_f16x2(v1.x, v1.y);
          xa[mt][kk][2] = pack_f16x2(v2.x, v2.y);
          xa[mt][kk][3] = pack_f16x2(v3.x, v3.y);
        }
#pragma unroll
      for (int r4 = 0; r4 < 4; ++r4) px[r4] += tstride;

      // ---- x-path GEMM: gi = x @ Wih^T (24 ldsm4, 96 mma; depth-1 prefetch) ----
      uint32_t bcur[4], bnext[4];
      ldsm4(bcur, wih_b);  // idx 0: kk=0,u=0
#pragma unroll
      for (int idx = 0; idx < 24; ++idx) {
        if (idx < 23) {
          const int nkk = (idx + 1) / 6, nu = (idx + 1) % 6;
          ldsm4(bnext, wih_b + (64 * (nu >> 1) + 16 * (nu & 1)) * (PITCH * 2) + nkk * 32);
        }
        const int kk = idx / 6, u = idx % 6;
        const int g = u >> 1, jj0 = (u & 1) * 2;
#pragma unroll
        for (int mt = 0; mt < 2; ++mt) {
          float* d0 = (g == 0) ? accR[mt * 4 + jj0] : (g == 1) ? accZ[mt * 4 + jj0] : accN[mt * 4 + jj0];
          float* d1 = (g == 0) ? accR[mt * 4 + jj0 + 1] : (g == 1) ? accZ[mt * 4 + jj0 + 1] : accN[mt * 4 + jj0 + 1];
          mma16816(d0, xa[mt][kk], bcur[0], bcur[1]);
          mma16816(d1, xa[mt][kk], bcur[2], bcur[3]);
        }
        bcur[0] = bnext[0]; bcur[1] = bnext[1];
        bcur[2] = bnext[2]; bcur[3] = bnext[3];
      }
    }  // xa dies here

    // ---- publish this warp's h columns to the pair buffer (16 STS.32) ----
#pragma unroll
    for (int mt = 0; mt < 2; ++mt)
#pragma unroll
      for (int jj = 0; jj < 4; ++jj) {
        __half* pa = hx + (16 * mt + lr) * PITCH + 32 * q + 8 * jj + c0;
        __half* pb = hx + (16 * mt + lr + 8) * PITCH + 32 * q + 8 * jj + c0;
        *reinterpret_cast<uint32_t*>(pa) = pack_f16x2(hf[mt * 4 + jj][0], hf[mt * 4 + jj][1]);
        *reinterpret_cast<uint32_t*>(pb) = pack_f16x2(hf[mt * 4 + jj][2], hf[mt * 4 + jj][3]);
      }
    asm volatile("bar.sync %0, %1;" :: "r"(barid), "r"(64) : "memory");

    // ---- load full-h A-fragments (8 ldsm4), then release the buffer ----
    uint32_t ha[2][4][4];
#pragma unroll
    for (int mt = 0; mt < 2; ++mt)
#pragma unroll
      for (int kk = 0; kk < 4; ++kk)
        ldsm4(ha[mt][kk], hx_u32 + mt * 16 * (PITCH * 2) + hx_a_off + kk * 32);
    asm volatile("bar.sync %0, %1;" :: "r"(barid), "r"(64) : "memory");

    // ---- h-path GEMM: gh = h @ Whh^T (24 ldsm4, 96 mma; depth-1 prefetch) ----
    {
      uint32_t bcur[4], bnext[4];
      ldsm4(bcur, whh_b);
#pragma unroll
      for (int idx = 0; idx < 24; ++idx) {
        if (idx < 23) {
          const int nkk = (idx + 1) / 6, nu = (idx + 1) % 6;
          ldsm4(bnext, whh_b + (64 * (nu >> 1) + 16 * (nu & 1)) * (PITCH * 2) + nkk * 32);
        }
        const int kk = idx / 6, u = idx % 6;
        const int g = u >> 1, jj0 = (u & 1) * 2;
#pragma unroll
        for (int mt = 0; mt < 2; ++mt) {
          float* d0 = (g == 0) ? accR[mt * 4 + jj0] : (g == 1) ? accZ[mt * 4 + jj0] : accHN[mt * 4 + jj0];
          float* d1 = (g == 0) ? accR[mt * 4 + jj0 + 1] : (g == 1) ? accZ[mt * 4 + jj0 + 1] : accHN[mt * 4 + jj0 + 1];
          mma16816(d0, ha[mt][kk], bcur[0], bcur[1]);
          mma16816(d1, ha[mt][kk], bcur[2], bcur[3]);
        }
        bcur[0] = bnext[0]; bcur[1] = bnext[1];
        bcur[2] = bnext[2]; bcur[3] = bnext[3];
      }
    }

    // ---- elementwise GRU update via MUFU.TANH (v9 numerics) ----
#pragma unroll
    for (int jj = 0; jj < 4; ++jj) {
      const int col = 32 * q + 8 * jj + c0;
      const float2 bR = *reinterpret_cast<const float2*>(brz + col);
      const float2 bZ = *reinterpret_cast<const float2*>(brz + 64 + col);
      const float2 bN = *reinterpret_cast<const float2*>(bin_s + col);
      const float2 bHN = *reinterpret_cast<const float2*>(bhn_s + col);
#pragma unroll
      for (int mt = 0; mt < 2; ++mt) {
        const int j = mt * 4 + jj;
#pragma unroll
        for (int e = 0; e < 4; ++e) {
          const float br = (e & 1) ? bR.y : bR.x;
          const float bz = (e & 1) ? bZ.y : bZ.x;
          const float bn = (e & 1) ? bN.y : bN.x;
          const float bhn = (e & 1) ? bHN.y : bHN.x;
          const float r = fsigmoid_half(fmaf(0.5f, accR[j][e], br));
          const float z = fsigmoid_half(fmaf(0.5f, accZ[j][e], bz));
          const float n = ftanh(accN[j][e] + bn + r * (accHN[j][e] + bhn));
          hf[j][e] = n + z * (hf[j][e] - n);
        }
      }
    }
  }

  // ---- write final h (f32 state, exact): this warp's 32 cols x 32 rows ----
#pragma unroll
  for (int mt = 0; mt < 2; ++mt)
#pragma unroll
    for (int jj = 0; jj < 4; ++jj) {
      const int j = mt * 4 + jj;
      float* poa = out + (size_t)(pr0 + 16 * mt + lr) * kH + 32 * q + 8 * jj + c0;
      float* pob = out + (size_t)(pr0 + 16 * mt + lr + 8) * kH + 32 * q + 8 * jj + c0;
      float2 va, vb;
      va.x = hf[j][0]; va.y = hf[j][1];
      vb.x = hf[j][2]; vb.y = hf[j][3];
      *reinterpret_cast<float2*>(poa) = va;
      *reinterpret_cast<float2*>(pob) = vb;
    }
}

extern "C" void kernel_launch(void* const* d_in, const int* in_sizes, int n_in,
                              void* d_out, int out_size) {
  const float* chars = (const float*)d_in[0];
  const float* Wih = (const float*)d_in[1];
  const float* Whh = (const float*)d_in[2];
  const float* bih = (const float*)d_in[3];
  const float* bhh = (const float*)d_in[4];
  float* out = (float*)d_out;

  cudaFuncSetAttribute(gru_fused_kernel,
                       cudaFuncAttributeMaxDynamicSharedMemorySize, SMEM_BYTES);

  const int grid = NROWS / 128;  // 250 CTAs, 4 pairs x 32 rows each
  gru_fused_kernel<<<grid, THREADS, SMEM_BYTES>>>(chars, Wih, Whh, bih, bhh, out);
}